// round 4
// baseline (speedup 1.0000x reference)
#include <cuda_runtime.h>
#include <cuda_bf16.h>
#include <stdint.h>
#include <math.h>

#define DI __device__ __forceinline__

typedef __nv_bfloat16 bf16;

// Problem dims
#define B_   256
#define S_   48
#define I_   2048
#define H_   2048
#define O_   1024
#define HOR  12
#define G4   (4 * H_)       // 8192 gate rows
#define KT   (I_ + H_)      // 4096 combined K

// ---------------- static device scratch (allocation-free) ----------------
__device__ bf16  g_Wc_hi[G4 * KT];          // combined [8192][4096]  (W_ih | W_hh), hi split
__device__ bf16  g_Wc_lo[G4 * KT];          // lo split
__device__ bf16  g_Wfc_hi[O_ * H_];
__device__ bf16  g_Wfc_lo[O_ * H_];
__device__ float g_bias[G4];                // b_ih + b_hh
__device__ bf16  g_x_hi[B_ * S_ * I_];
__device__ bf16  g_x_lo[B_ * S_ * I_];
__device__ bf16  g_h_hi[2][B_ * H_];        // double-buffered hidden state (bf16 splits)
__device__ bf16  g_h_lo[2][B_ * H_];
__device__ float g_c[B_ * H_];              // cell state fp32
__device__ bf16  g_di_hi[B_ * I_];          // decoder input [out | zeros], splits
__device__ bf16  g_di_lo[B_ * I_];

// ---------------- helpers ----------------
DI void split2(float w, bf16& hi, bf16& lo) {
    bf16 h = __float2bfloat16(w);
    hi = h;
    lo = __float2bfloat16(w - __bfloat162float(h));
}

DI uint32_t sptr(const void* p) {
    return (uint32_t)__cvta_generic_to_shared((void*)p);
}

DI void cp16(bf16* dst, const bf16* src) {
    asm volatile("cp.async.cg.shared.global [%0], [%1], 16;\n"
                 :: "r"(sptr(dst)), "l"((const void*)src));
}
DI void cp_commit() { asm volatile("cp.async.commit_group;\n"); }
template <int N>
DI void cp_wait() { asm volatile("cp.async.wait_group %0;\n" :: "n"(N)); }

DI void ldsm4(uint32_t& r0, uint32_t& r1, uint32_t& r2, uint32_t& r3, const bf16* p) {
    asm volatile("ldmatrix.sync.aligned.m8n8.x4.shared.b16 {%0,%1,%2,%3}, [%4];\n"
                 : "=r"(r0), "=r"(r1), "=r"(r2), "=r"(r3)
                 : "r"(sptr(p)));
}

DI void mma16816(float* d, uint32_t a0, uint32_t a1, uint32_t a2, uint32_t a3,
                 uint32_t b0, uint32_t b1) {
    asm volatile("mma.sync.aligned.m16n8k16.row.col.f32.bf16.bf16.f32 "
                 "{%0,%1,%2,%3}, {%4,%5,%6,%7}, {%8,%9}, {%0,%1,%2,%3};\n"
                 : "+f"(d[0]), "+f"(d[1]), "+f"(d[2]), "+f"(d[3])
                 : "r"(a0), "r"(a1), "r"(a2), "r"(a3), "r"(b0), "r"(b1));
}

DI float sigm(float x) { return 1.0f / (1.0f + expf(-x)); }

// ---------------- prep kernels ----------------
__global__ void prep_wc_kernel(const float* __restrict__ W_ih, const float* __restrict__ W_hh) {
    const int total = G4 * KT;
    for (int idx = blockIdx.x * blockDim.x + threadIdx.x; idx < total;
         idx += gridDim.x * blockDim.x) {
        int r = idx >> 12;         // / 4096
        int k = idx & 4095;
        float w = (k < I_) ? W_ih[r * I_ + k] : W_hh[r * H_ + (k - I_)];
        split2(w, g_Wc_hi[idx], g_Wc_lo[idx]);
    }
}

__global__ void prep_wfc_kernel(const float* __restrict__ W_fc) {
    const int total = O_ * H_;
    for (int idx = blockIdx.x * blockDim.x + threadIdx.x; idx < total;
         idx += gridDim.x * blockDim.x) {
        split2(W_fc[idx], g_Wfc_hi[idx], g_Wfc_lo[idx]);
    }
}

__global__ void prep_x_kernel(const float* __restrict__ x) {
    const int total = B_ * S_ * I_;
    for (int idx = blockIdx.x * blockDim.x + threadIdx.x; idx < total;
         idx += gridDim.x * blockDim.x) {
        split2(x[idx], g_x_hi[idx], g_x_lo[idx]);
    }
}

__global__ void prep_state_kernel(const float* __restrict__ b_ih, const float* __restrict__ b_hh) {
    const int total = B_ * H_;           // == B_*I_
    bf16 z = __float2bfloat16(0.0f);
    for (int idx = blockIdx.x * blockDim.x + threadIdx.x; idx < total;
         idx += gridDim.x * blockDim.x) {
        g_h_hi[0][idx] = z;
        g_h_lo[0][idx] = z;
        g_c[idx] = 0.0f;
        g_di_hi[idx] = z;
        g_di_lo[idx] = z;
        if (idx < G4) g_bias[idx] = b_ih[idx] + b_hh[idx];
    }
}

// ---------------- fused gate-GEMM + LSTM cell kernel ----------------
// CTA tile: BM=64 rows of batch, BN=64 columns of H, for ALL 4 gates (256 B-rows).
// K = 4096 (seg0: x_t or decoder input, seg1: h). 3-way bf16 split MMA:
// acc = Ah*Bh + Ah*Bl + Al*Bh  (Al*Bl term ~1e-5 relative, dropped).
#define BM    64
#define BN    64
#define KC    32
#define LDT   40                      // padded smem tile stride (bf16 elems), 80B rows
#define A_ELE (BM * LDT)              // 2560
#define B_ELE (256 * LDT)             // 10240
#define STAGE_ELE (2 * A_ELE + 2 * B_ELE)   // 25600 bf16
#define SMEM_GC_BYTES (2 * STAGE_ELE * 2)   // 102400 bytes

DI void gc_load_stage(bf16* st, int k0, int m0, int n0,
                      const bf16* a0_hi, const bf16* a0_lo, int lda0,
                      const bf16* h_hi, const bf16* h_lo, int tid) {
    const bf16* pah;
    const bf16* pal;
    int lda;
    if (k0 < I_) { pah = a0_hi + k0;        pal = a0_lo + k0;        lda = lda0; }
    else         { pah = h_hi + (k0 - I_);  pal = h_lo + (k0 - I_);  lda = H_;   }
    // A tile: 64 rows x 32 cols x 2 splits = 512 x 16B chunks -> 2 per thread
#pragma unroll
    for (int u = 0; u < 2; u++) {
        int cid = u * 256 + tid;
        int split = cid >> 8;
        int rem = cid & 255;
        int row = rem >> 2, cb = rem & 3;
        const bf16* src = (split ? pal : pah) + (size_t)(m0 + row) * lda + cb * 8;
        cp16(st + split * A_ELE + row * LDT + cb * 8, src);
    }
    // B tile: 256 gate-rows x 32 cols x 2 splits = 2048 chunks -> 8 per thread
#pragma unroll
    for (int u = 0; u < 8; u++) {
        int cid = u * 256 + tid;
        int split = cid >> 10;
        int rem = cid & 1023;
        int brow = rem >> 2, cb = rem & 3;
        int grow = ((brow >> 6) * H_) + n0 + (brow & 63);     // gate*H + col
        const bf16* src = (split ? g_Wc_lo : g_Wc_hi) + (size_t)grow * KT + k0 + cb * 8;
        cp16(st + 2 * A_ELE + split * B_ELE + brow * LDT + cb * 8, src);
    }
}

__global__ __launch_bounds__(256, 1)
void gemm_cell_kernel(int t, int mode, int par) {
    extern __shared__ bf16 smem[];
    const int tid = threadIdx.x;
    const int n0 = blockIdx.x * BN;     // column within H
    const int m0 = blockIdx.y * BM;     // batch row

    const bf16* a0_hi;
    const bf16* a0_lo;
    int lda0;
    if (mode == 0) {
        a0_hi = g_x_hi + (size_t)t * I_;
        a0_lo = g_x_lo + (size_t)t * I_;
        lda0 = S_ * I_;
    } else {
        a0_hi = g_di_hi;
        a0_lo = g_di_lo;
        lda0 = I_;
    }
    const bf16* h_hi = g_h_hi[par];
    const bf16* h_lo = g_h_lo[par];
    bf16* hn_hi = g_h_hi[par ^ 1];
    bf16* hn_lo = g_h_lo[par ^ 1];

    const int wid = tid >> 5, lane = tid & 31;
    const int wm = wid >> 2, wn = wid & 3;   // 2 x 4 warp grid, warp tile 32 x 64

    float acc[2][8][4];
#pragma unroll
    for (int i = 0; i < 2; i++)
#pragma unroll
        for (int j = 0; j < 8; j++)
#pragma unroll
            for (int q = 0; q < 4; q++) acc[i][j][q] = 0.0f;

    const int NS = KT / KC;   // 128 stages

    gc_load_stage(smem, 0, m0, n0, a0_hi, a0_lo, lda0, h_hi, h_lo, tid);
    cp_commit();

    for (int s = 0; s < NS; s++) {
        if (s + 1 < NS) {
            gc_load_stage(smem + ((s + 1) & 1) * STAGE_ELE, (s + 1) * KC, m0, n0,
                          a0_hi, a0_lo, lda0, h_hi, h_lo, tid);
            cp_commit();
            cp_wait<1>();
        } else {
            cp_wait<0>();
        }
        __syncthreads();

        bf16* st = smem + (s & 1) * STAGE_ELE;
        const bf16* Ah = st;
        const bf16* Al = st + A_ELE;
        const bf16* Bh = st + 2 * A_ELE;
        const bf16* Bl = st + 2 * A_ELE + B_ELE;

#pragma unroll
        for (int kk = 0; kk < KC; kk += 16) {
            uint32_t ah[2][4], al[2][4];
#pragma unroll
            for (int i = 0; i < 2; i++) {
                int row = wm * 32 + i * 16 + (lane & 15);
                int col = kk + ((lane >> 4) << 3);
                ldsm4(ah[i][0], ah[i][1], ah[i][2], ah[i][3], Ah + row * LDT + col);
                ldsm4(al[i][0], al[i][1], al[i][2], al[i][3], Al + row * LDT + col);
            }
#pragma unroll
            for (int jp = 0; jp < 4; jp++) {
                int brow = wn * 64 + jp * 16 + (lane & 7) + ((lane >> 4) << 3);
                int col = kk + (((lane >> 3) & 1) << 3);
                uint32_t bh[4], bl[4];
                ldsm4(bh[0], bh[1], bh[2], bh[3], Bh + brow * LDT + col);
                ldsm4(bl[0], bl[1], bl[2], bl[3], Bl + brow * LDT + col);
#pragma unroll
                for (int i = 0; i < 2; i++) {
#pragma unroll
                    for (int q = 0; q < 2; q++) {
                        float* d = acc[i][jp * 2 + q];
                        mma16816(d, ah[i][0], ah[i][1], ah[i][2], ah[i][3], bh[2*q], bh[2*q+1]);
                        mma16816(d, ah[i][0], ah[i][1], ah[i][2], ah[i][3], bl[2*q], bl[2*q+1]);
                        mma16816(d, al[i][0], al[i][1], al[i][2], al[i][3], bh[2*q], bh[2*q+1]);
                    }
                }
            }
        }
        __syncthreads();
    }

    // ---- epilogue: accumulate gates in smem, apply LSTM cell ----
    float* gs = (float*)smem;   // [64][256] fp32 = 64KB (smem reuse, all compute done)
#pragma unroll
    for (int i = 0; i < 2; i++) {
#pragma unroll
        for (int j = 0; j < 8; j++) {
            int r = wm * 32 + i * 16 + (lane >> 2);
            int col = wn * 64 + j * 8 + ((lane & 3) << 1);
            gs[r * 256 + col]           = acc[i][j][0];
            gs[r * 256 + col + 1]       = acc[i][j][1];
            gs[(r + 8) * 256 + col]     = acc[i][j][2];
            gs[(r + 8) * 256 + col + 1] = acc[i][j][3];
        }
    }
    __syncthreads();

#pragma unroll
    for (int e = 0; e < 16; e++) {
        int idx = e * 256 + tid;
        int r = idx >> 6, j = idx & 63;
        float iv = gs[r * 256 + j]        + g_bias[0 * H_ + n0 + j];
        float fv = gs[r * 256 + 64 + j]   + g_bias[1 * H_ + n0 + j];
        float gv = gs[r * 256 + 128 + j]  + g_bias[2 * H_ + n0 + j];
        float ov = gs[r * 256 + 192 + j]  + g_bias[3 * H_ + n0 + j];
        int gi = (m0 + r) * H_ + n0 + j;
        float cold = g_c[gi];
        float cn = sigm(fv) * cold + sigm(iv) * tanhf(gv);
        float hn = sigm(ov) * tanhf(cn);
        g_c[gi] = cn;
        split2(hn, hn_hi[gi], hn_lo[gi]);
    }
}

// ---------------- decoder FC kernel: out = h @ W_fc^T + b_fc ----------------
// M=256, N=1024, K=2048. CTA tile 64x64, warp tile 32x16. Writes d_out slice
// and decoder-input splits (cols [0,1024) of g_di; [1024,2048) stay zero).
#define FA_ELE (64 * LDT)   // 2560

__global__ __launch_bounds__(256, 1)
void fc_kernel(float* __restrict__ out, const float* __restrict__ b_fc, int t, int par) {
    __shared__ bf16 fsm[2 * 4 * FA_ELE];   // 2 stages x (Ahi,Alo,Bhi,Blo) x 2560 = 40KB
    const int tid = threadIdx.x;
    const int n0 = blockIdx.x * 64;
    const int m0 = blockIdx.y * 64;
    const bf16* h_hi = g_h_hi[par];
    const bf16* h_lo = g_h_lo[par];

    const int wid = tid >> 5, lane = tid & 31;
    const int wm = wid >> 2, wn = wid & 3;

    float acc[2][2][4];
#pragma unroll
    for (int i = 0; i < 2; i++)
#pragma unroll
        for (int j = 0; j < 2; j++)
#pragma unroll
            for (int q = 0; q < 4; q++) acc[i][j][q] = 0.0f;

    const int NS = H_ / KC;   // 64

    // stage loader: A(64x32 hi/lo) + B(64x32 hi/lo) = 1024 chunks -> 4/thread
    auto load_fc = [&](int buf, int k0) {
        bf16* st = fsm + buf * 4 * FA_ELE;
#pragma unroll
        for (int u = 0; u < 2; u++) {
            int cid = u * 256 + tid;
            int split = cid >> 8;
            int rem = cid & 255;
            int row = rem >> 2, cb = rem & 3;
            const bf16* src = (split ? h_lo : h_hi) + (size_t)(m0 + row) * H_ + k0 + cb * 8;
            cp16(st + split * FA_ELE + row * LDT + cb * 8, src);
        }
#pragma unroll
        for (int u = 0; u < 2; u++) {
            int cid = u * 256 + tid;
            int split = cid >> 8;
            int rem = cid & 255;
            int row = rem >> 2, cb = rem & 3;
            const bf16* src = (split ? g_Wfc_lo : g_Wfc_hi) + (size_t)(n0 + row) * H_ + k0 + cb * 8;
            cp16(st + 2 * FA_ELE + split * FA_ELE + row * LDT + cb * 8, src);
        }
    };

    load_fc(0, 0);
    cp_commit();

    for (int s = 0; s < NS; s++) {
        if (s + 1 < NS) {
            load_fc((s + 1) & 1, (s + 1) * KC);
            cp_commit();
            cp_wait<1>();
        } else {
            cp_wait<0>();
        }
        __syncthreads();

        bf16* st = fsm + (s & 1) * 4 * FA_ELE;
        const bf16* Ah = st;
        const bf16* Al = st + FA_ELE;
        const bf16* Bh = st + 2 * FA_ELE;
        const bf16* Bl = st + 3 * FA_ELE;

#pragma unroll
        for (int kk = 0; kk < KC; kk += 16) {
            uint32_t ah[2][4], al[2][4];
#pragma unroll
            for (int i = 0; i < 2; i++) {
                int row = wm * 32 + i * 16 + (lane & 15);
                int col = kk + ((lane >> 4) << 3);
                ldsm4(ah[i][0], ah[i][1], ah[i][2], ah[i][3], Ah + row * LDT + col);
                ldsm4(al[i][0], al[i][1], al[i][2], al[i][3], Al + row * LDT + col);
            }
            int brow = wn * 16 + (lane & 7) + ((lane >> 4) << 3);
            int col = kk + (((lane >> 3) & 1) << 3);
            uint32_t bh[4], bl[4];
            ldsm4(bh[0], bh[1], bh[2], bh[3], Bh + brow * LDT + col);
            ldsm4(bl[0], bl[1], bl[2], bl[3], Bl + brow * LDT + col);
#pragma unroll
            for (int i = 0; i < 2; i++) {
#pragma unroll
                for (int q = 0; q < 2; q++) {
                    float* d = acc[i][q];
                    mma16816(d, ah[i][0], ah[i][1], ah[i][2], ah[i][3], bh[2*q], bh[2*q+1]);
                    mma16816(d, ah[i][0], ah[i][1], ah[i][2], ah[i][3], bl[2*q], bl[2*q+1]);
                    mma16816(d, al[i][0], al[i][1], al[i][2], al[i][3], bh[2*q], bh[2*q+1]);
                }
            }
        }
        __syncthreads();
    }

    // epilogue: write fp32 to out[b][t][o] and bf16 splits to decoder input
#pragma unroll
    for (int i = 0; i < 2; i++) {
#pragma unroll
        for (int j = 0; j < 2; j++) {
            int r0 = m0 + wm * 32 + i * 16 + (lane >> 2);
            int c0 = n0 + wn * 16 + j * 8 + ((lane & 3) << 1);
#pragma unroll
            for (int half = 0; half < 2; half++) {
                int r = r0 + half * 8;
                float v0 = acc[i][j][half * 2]     + b_fc[c0];
                float v1 = acc[i][j][half * 2 + 1] + b_fc[c0 + 1];
                out[(size_t)r * (HOR * O_) + t * O_ + c0]     = v0;
                out[(size_t)r * (HOR * O_) + t * O_ + c0 + 1] = v1;
                split2(v0, g_di_hi[r * I_ + c0],     g_di_lo[r * I_ + c0]);
                split2(v1, g_di_hi[r * I_ + c0 + 1], g_di_lo[r * I_ + c0 + 1]);
            }
        }
    }
}

// ---------------- launch ----------------
extern "C" void kernel_launch(void* const* d_in, const int* in_sizes, int n_in,
                              void* d_out, int out_size) {
    const float* x    = (const float*)d_in[0];
    const float* W_ih = (const float*)d_in[1];
    const float* W_hh = (const float*)d_in[2];
    const float* b_ih = (const float*)d_in[3];
    const float* b_hh = (const float*)d_in[4];
    const float* W_fc = (const float*)d_in[5];
    const float* b_fc = (const float*)d_in[6];
    float* out = (float*)d_out;

    cudaFuncSetAttribute(gemm_cell_kernel,
                         cudaFuncAttributeMaxDynamicSharedMemorySize, SMEM_GC_BYTES);

    prep_wc_kernel<<<2048, 256>>>(W_ih, W_hh);
    prep_wfc_kernel<<<512, 256>>>(W_fc);
    prep_x_kernel<<<2048, 256>>>(x);
    prep_state_kernel<<<512, 256>>>(b_ih, b_hh);

    dim3 ggrid(H_ / BN, B_ / BM);   // (32, 4) = 128 CTAs
    dim3 fgrid(O_ / 64, B_ / 64);   // (16, 4)

    int par = 0;
    for (int t = 0; t < S_; t++) {
        gemm_cell_kernel<<<ggrid, 256, SMEM_GC_BYTES>>>(t, 0, par);
        par ^= 1;
    }
    for (int d = 0; d < HOR; d++) {
        fc_kernel<<<fgrid, 256>>>(out, b_fc, d, par);
        gemm_cell_kernel<<<ggrid, 256, SMEM_GC_BYTES>>>(0, 1, par);
        par ^= 1;
    }
}

// round 6
// speedup vs baseline: 1.0082x; 1.0082x over previous
#include <cuda_runtime.h>
#include <cuda_bf16.h>
#include <stdint.h>
#include <math.h>

#define DI __device__ __forceinline__

typedef __nv_bfloat16 bf16;

// Problem dims
#define B_   256
#define S_   48
#define I_   2048
#define H_   2048
#define O_   1024
#define HOR  12
#define G4   (4 * H_)       // 8192 gate rows
#define KT   (I_ + H_)      // 4096 combined K
#define KC   32
#define NS_GATE (KT / KC)   // 128 k-stages for gate GEMM
#define NS_FC   (H_ / KC)   // 64 k-stages for FC GEMM

// ---------------- static device scratch (allocation-free) ----------------
// Weights tiled: [n_tile(32)][split(2)][stage(128)][brow(256)][kc(32)]
// -> each CTA streams a fully CONTIGUOUS 2MB run per split.
__device__ bf16  g_Wct[32u * 2 * 128 * 256 * 32];     // 67.1M elems = 134 MB
// FC weights tiled: [n_tile(16)][split(2)][stage(64)][row(64)][kc(32)]
__device__ bf16  g_Wfct[16u * 2 * 64 * 64 * 32];      // 4M elems
__device__ float g_bias[G4];                          // b_ih + b_hh
// x tiled: [t(48)][stage(64)][b(256)][kc(32)] hi/lo
__device__ bf16  g_xt_hi[48u * 64 * 256 * 32];
__device__ bf16  g_xt_lo[48u * 64 * 256 * 32];
// h tiled (double buffered): [par][stage(64)][b(256)][kc(32)]
__device__ bf16  g_ht_hi[2][64 * 256 * 32];
__device__ bf16  g_ht_lo[2][64 * 256 * 32];
__device__ float g_c[B_ * H_];                        // cell state fp32 [b][col]
// decoder input tiled: [stage(64)][b(256)][kc(32)]; stages 32..63 stay zero
__device__ bf16  g_dit_hi[64 * 256 * 32];
__device__ bf16  g_dit_lo[64 * 256 * 32];

// ---------------- helpers ----------------
DI void split2(float w, bf16& hi, bf16& lo) {
    bf16 h = __float2bfloat16(w);
    hi = h;
    lo = __float2bfloat16(w - __bfloat162float(h));
}

DI uint32_t sptr(const void* p) {
    return (uint32_t)__cvta_generic_to_shared((void*)p);
}

DI void cp16(bf16* dst, const bf16* src) {
    asm volatile("cp.async.cg.shared.global [%0], [%1], 16;\n"
                 :: "r"(sptr(dst)), "l"((const void*)src));
}
DI void cp_commit() { asm volatile("cp.async.commit_group;\n"); }
template <int N>
DI void cp_wait() { asm volatile("cp.async.wait_group %0;\n" :: "n"(N)); }

DI void ldsm4(uint32_t& r0, uint32_t& r1, uint32_t& r2, uint32_t& r3, const bf16* p) {
    asm volatile("ldmatrix.sync.aligned.m8n8.x4.shared.b16 {%0,%1,%2,%3}, [%4];\n"
                 : "=r"(r0), "=r"(r1), "=r"(r2), "=r"(r3)
                 : "r"(sptr(p)));
}

DI void mma16816(float* d, uint32_t a0, uint32_t a1, uint32_t a2, uint32_t a3,
                 uint32_t b0, uint32_t b1) {
    asm volatile("mma.sync.aligned.m16n8k16.row.col.f32.bf16.bf16.f32 "
                 "{%0,%1,%2,%3}, {%4,%5,%6,%7}, {%8,%9}, {%0,%1,%2,%3};\n"
                 : "+f"(d[0]), "+f"(d[1]), "+f"(d[2]), "+f"(d[3])
                 : "r"(a0), "r"(a1), "r"(a2), "r"(a3), "r"(b0), "r"(b1));
}

DI float sigm(float x) { return 1.0f / (1.0f + expf(-x)); }

// ---------------- prep kernels ----------------
// Gate weights: dst-linear over pairs; writes hi and lo tiled blocks.
__global__ void prep_wc_kernel(const float* __restrict__ W_ih, const float* __restrict__ W_hh) {
    const unsigned total = 32u * 128 * 256 * 32;   // 33.55M pairs (per split-pair)
    for (unsigned p = blockIdx.x * blockDim.x + threadIdx.x; p < total;
         p += gridDim.x * blockDim.x) {
        unsigned ntile = p >> 20;                 // / (128*8192)
        unsigned r20 = p & 1048575u;
        unsigned stage = r20 >> 13;               // / 8192
        unsigned off = r20 & 8191u;               // brow*32 + kc
        unsigned brow = off >> 5, kc = off & 31u;
        unsigned row = (brow >> 6) * H_ + ntile * 64 + (brow & 63u);  // gate*H + col
        unsigned k = stage * KC + kc;
        float w = (k < I_) ? W_ih[(size_t)row * I_ + k] : W_hh[(size_t)row * H_ + (k - I_)];
        size_t dhi = ((size_t)(ntile * 2 + 0) * 128 + stage) * 8192 + off;
        size_t dlo = ((size_t)(ntile * 2 + 1) * 128 + stage) * 8192 + off;
        bf16 hi, lo; split2(w, hi, lo);
        g_Wct[dhi] = hi;
        g_Wct[dlo] = lo;
    }
}

__global__ void prep_wfc_kernel(const float* __restrict__ W_fc) {
    const unsigned total = 16u * 64 * 64 * 32;    // 2.1M pairs
    for (unsigned p = blockIdx.x * blockDim.x + threadIdx.x; p < total;
         p += gridDim.x * blockDim.x) {
        unsigned ntile = p >> 17;                 // / (64*2048)
        unsigned rem = p & 131071u;
        unsigned stage = rem >> 11;               // / 2048
        unsigned off = rem & 2047u;               // row*32 + kc
        unsigned row = off >> 5, kc = off & 31u;
        float w = W_fc[(size_t)(ntile * 64 + row) * H_ + stage * KC + kc];
        size_t dhi = ((size_t)(ntile * 2 + 0) * 64 + stage) * 2048 + off;
        size_t dlo = ((size_t)(ntile * 2 + 1) * 64 + stage) * 2048 + off;
        bf16 hi, lo; split2(w, hi, lo);
        g_Wfct[dhi] = hi;
        g_Wfct[dlo] = lo;
    }
}

__global__ void prep_x_kernel(const float* __restrict__ x) {
    const unsigned total = 48u * 64 * 256 * 32;   // 25.2M
    for (unsigned p = blockIdx.x * blockDim.x + threadIdx.x; p < total;
         p += gridDim.x * blockDim.x) {
        unsigned t = p >> 19;                     // / 524288
        unsigned rem = p & 524287u;
        unsigned stage = rem >> 13;               // / 8192
        unsigned off = rem & 8191u;
        unsigned b = off >> 5, kc = off & 31u;
        float v = x[((size_t)b * S_ + t) * I_ + stage * KC + kc];
        split2(v, g_xt_hi[p], g_xt_lo[p]);
    }
}

__global__ void prep_state_kernel(const float* __restrict__ b_ih, const float* __restrict__ b_hh) {
    const int total = 64 * 256 * 32;              // 524288
    bf16 z = __float2bfloat16(0.0f);
    for (int idx = blockIdx.x * blockDim.x + threadIdx.x; idx < total;
         idx += gridDim.x * blockDim.x) {
        g_ht_hi[0][idx] = z;
        g_ht_lo[0][idx] = z;
        g_c[idx] = 0.0f;
        g_dit_hi[idx] = z;
        g_dit_lo[idx] = z;
        if (idx < G4) g_bias[idx] = b_ih[idx] + b_hh[idx];
    }
}

// ---------------- fused gate-GEMM + LSTM cell kernel ----------------
// CTA tile: BM=64 batch rows x BN=64 H-cols x 4 gates (256 B-rows). K=4096.
// 3-way bf16 split: acc = Ah*Bh + Ah*Bl + Al*Bh.
// 4-stage cp.async pipeline, all global streams contiguous (pre-tiled layouts).
#define BM    64
#define BN    64
#define LDT   40                      // padded smem row stride (bf16), 80B
#define A_ELE (BM * LDT)              // 2560
#define B_ELE (256 * LDT)             // 10240
#define STAGE_ELE (2 * A_ELE + 2 * B_ELE)   // 25600 bf16 = 51200 B
#define NSTG  4
#define SMEM_GC_BYTES (NSTG * STAGE_ELE * 2)   // 204800 bytes

DI void gc_load_stage(bf16* st, int s, int m0, int ntile,
                      const bf16* axh, const bf16* axl,
                      const bf16* hh, const bf16* hl, int tid) {
    // A source: stage block [256 b][32 kc], contiguous
    const bf16* pah;
    const bf16* pal;
    if (s < 64) { pah = axh + (size_t)s * 8192;        pal = axl + (size_t)s * 8192; }
    else        { pah = hh + (size_t)(s - 64) * 8192;  pal = hl + (size_t)(s - 64) * 8192; }
    // A tile: 64 rows x 32 k x 2 splits = 512 x 16B chunks -> 2 per thread
#pragma unroll
    for (int u = 0; u < 2; u++) {
        int cid = u * 256 + tid;
        int split = cid >> 8;
        int w = cid & 255;                       // row*4 + cb
        const bf16* src = (split ? pal : pah) + m0 * KC + w * 8;
        cp16(st + split * A_ELE + (w >> 2) * LDT + (w & 3) * 8, src);
    }
    // B tile: contiguous 8192-elem stage block per split -> 2048 chunks, 8/thread
#pragma unroll
    for (int u = 0; u < 8; u++) {
        int cid = u * 256 + tid;
        int split = cid >> 10;
        int w = cid & 1023;                      // brow*4 + cb
        const bf16* src = g_Wct + ((size_t)(ntile * 2 + split) * 128 + s) * 8192 + w * 8;
        cp16(st + 2 * A_ELE + split * B_ELE + (w >> 2) * LDT + (w & 3) * 8, src);
    }
}

__global__ __launch_bounds__(256, 1)
void gemm_cell_kernel(int t, int mode, int par) {
    extern __shared__ bf16 smem[];
    const int tid = threadIdx.x;
    const int ntile = blockIdx.x;
    const int n0 = ntile * BN;          // column within H
    const int m0 = blockIdx.y * BM;     // batch row

    const bf16* axh;
    const bf16* axl;
    if (mode == 0) { axh = g_xt_hi + (size_t)t * 524288; axl = g_xt_lo + (size_t)t * 524288; }
    else           { axh = g_dit_hi;                     axl = g_dit_lo; }
    const bf16* hh = g_ht_hi[par];
    const bf16* hl = g_ht_lo[par];
    bf16* hnh = g_ht_hi[par ^ 1];
    bf16* hnl = g_ht_lo[par ^ 1];

    const int wid = tid >> 5, lane = tid & 31;
    const int wm = wid >> 2, wn = wid & 3;   // 2 x 4 warp grid, warp tile 32 x 64

    float acc[2][8][4];
#pragma unroll
    for (int i = 0; i < 2; i++)
#pragma unroll
        for (int j = 0; j < 8; j++)
#pragma unroll
            for (int q = 0; q < 4; q++) acc[i][j][q] = 0.0f;

    // prologue: prefetch NSTG-1 stages
#pragma unroll
    for (int p = 0; p < NSTG - 1; p++) {
        gc_load_stage(smem + p * STAGE_ELE, p, m0, ntile, axh, axl, hh, hl, tid);
        cp_commit();
    }

    for (int s = 0; s < NS_GATE; s++) {
        cp_wait<NSTG - 2>();
        __syncthreads();

        int nxt = s + NSTG - 1;
        if (nxt < NS_GATE)
            gc_load_stage(smem + (nxt % NSTG) * STAGE_ELE, nxt, m0, ntile,
                          axh, axl, hh, hl, tid);
        cp_commit();

        bf16* st = smem + (s % NSTG) * STAGE_ELE;
        const bf16* Ah = st;
        const bf16* Al = st + A_ELE;
        const bf16* Bh = st + 2 * A_ELE;
        const bf16* Bl = st + 2 * A_ELE + B_ELE;

#pragma unroll
        for (int kk = 0; kk < KC; kk += 16) {
            uint32_t ah[2][4], al[2][4];
#pragma unroll
            for (int i = 0; i < 2; i++) {
                int row = wm * 32 + i * 16 + (lane & 15);
                int col = kk + ((lane >> 4) << 3);
                ldsm4(ah[i][0], ah[i][1], ah[i][2], ah[i][3], Ah + row * LDT + col);
                ldsm4(al[i][0], al[i][1], al[i][2], al[i][3], Al + row * LDT + col);
            }
#pragma unroll
            for (int jp = 0; jp < 4; jp++) {
                int brow = wn * 64 + jp * 16 + (lane & 7) + ((lane >> 4) << 3);
                int col = kk + (((lane >> 3) & 1) << 3);
                uint32_t bh[4], bl[4];
                ldsm4(bh[0], bh[1], bh[2], bh[3], Bh + brow * LDT + col);
                ldsm4(bl[0], bl[1], bl[2], bl[3], Bl + brow * LDT + col);
#pragma unroll
                for (int i = 0; i < 2; i++) {
#pragma unroll
                    for (int q = 0; q < 2; q++) {
                        float* d = acc[i][jp * 2 + q];
                        mma16816(d, ah[i][0], ah[i][1], ah[i][2], ah[i][3], bh[2*q], bh[2*q+1]);
                        mma16816(d, ah[i][0], ah[i][1], ah[i][2], ah[i][3], bl[2*q], bl[2*q+1]);
                        mma16816(d, al[i][0], al[i][1], al[i][2], al[i][3], bh[2*q], bh[2*q+1]);
                    }
                }
            }
        }
    }
    __syncthreads();

    // ---- epilogue: gather gates in smem, apply LSTM cell ----
    float* gs = (float*)smem;   // [64][256] fp32 = 64KB (fits in stage buffers 0-1)
#pragma unroll
    for (int i = 0; i < 2; i++) {
#pragma unroll
        for (int j = 0; j < 8; j++) {
            int r = wm * 32 + i * 16 + (lane >> 2);
            int col = wn * 64 + j * 8 + ((lane & 3) << 1);
            gs[r * 256 + col]           = acc[i][j][0];
            gs[r * 256 + col + 1]       = acc[i][j][1];
            gs[(r + 8) * 256 + col]     = acc[i][j][2];
            gs[(r + 8) * 256 + col + 1] = acc[i][j][3];
        }
    }
    __syncthreads();

#pragma unroll
    for (int e = 0; e < 16; e++) {
        int idx = e * 256 + tid;
        int r = idx >> 6, j = idx & 63;
        float iv = gs[r * 256 + j]        + g_bias[0 * H_ + n0 + j];
        float fv = gs[r * 256 + 64 + j]   + g_bias[1 * H_ + n0 + j];
        float gv = gs[r * 256 + 128 + j]  + g_bias[2 * H_ + n0 + j];
        float ov = gs[r * 256 + 192 + j]  + g_bias[3 * H_ + n0 + j];
        int hcol = n0 + j;
        int gi = (m0 + r) * H_ + hcol;                       // c: [b][col] linear
        float cold = g_c[gi];
        float cn = sigm(fv) * cold + sigm(iv) * tanhf(gv);
        float hn = sigm(ov) * tanhf(cn);
        g_c[gi] = cn;
        int dt = ((hcol >> 5) * 256 + (m0 + r)) * 32 + (hcol & 31);   // tiled h
        split2(hn, hnh[dt], hnl[dt]);
    }
}

// ---------------- decoder FC kernel: out = h @ W_fc^T + b_fc ----------------
// M=256, N=1024, K=2048. CTA 64x64, warp 32x16. 4-stage pipeline, tiled streams.
#define FA_ELE (64 * LDT)                     // 2560
#define FSTAGE_ELE (4 * FA_ELE)               // 10240 bf16 = 20480 B
#define SMEM_FC_BYTES (NSTG * FSTAGE_ELE * 2) // 81920 bytes

DI void fc_load_stage(bf16* st, int s, int m0, int ntile,
                      const bf16* hh, const bf16* hl, int tid) {
    // 1024 chunks: quarter q: 0=Ah 1=Al 2=Bh 3=Bl; w = row*4+cb
#pragma unroll
    for (int u = 0; u < 4; u++) {
        int cid = u * 256 + tid;
        int q = cid >> 8;
        int w = cid & 255;
        const bf16* src;
        if (q < 2) {
            const bf16* p = (q ? hl : hh) + (size_t)s * 8192;
            src = p + m0 * KC + w * 8;
        } else {
            src = g_Wfct + ((size_t)(ntile * 2 + (q - 2)) * 64 + s) * 2048 + w * 8;
        }
        cp16(st + q * FA_ELE + (w >> 2) * LDT + (w & 3) * 8, src);
    }
}

__global__ __launch_bounds__(256, 1)
void fc_kernel(float* __restrict__ out, const float* __restrict__ b_fc, int t, int par) {
    extern __shared__ bf16 fsm[];
    const int tid = threadIdx.x;
    const int ntile = blockIdx.x;
    const int n0 = ntile * 64;
    const int m0 = blockIdx.y * 64;
    const bf16* hh = g_ht_hi[par];
    const bf16* hl = g_ht_lo[par];

    const int wid = tid >> 5, lane = tid & 31;
    const int wm = wid >> 2, wn = wid & 3;

    float acc[2][2][4];
#pragma unroll
    for (int i = 0; i < 2; i++)
#pragma unroll
        for (int j = 0; j < 2; j++)
#pragma unroll
            for (int q = 0; q < 4; q++) acc[i][j][q] = 0.0f;

#pragma unroll
    for (int p = 0; p < NSTG - 1; p++) {
        fc_load_stage(fsm + p * FSTAGE_ELE, p, m0, ntile, hh, hl, tid);
        cp_commit();
    }

    for (int s = 0; s < NS_FC; s++) {
        cp_wait<NSTG - 2>();
        __syncthreads();

        int nxt = s + NSTG - 1;
        if (nxt < NS_FC)
            fc_load_stage(fsm + (nxt % NSTG) * FSTAGE_ELE, nxt, m0, ntile, hh, hl, tid);
        cp_commit();

        bf16* st = fsm + (s % NSTG) * FSTAGE_ELE;
        const bf16* Ah = st;
        const bf16* Al = st + FA_ELE;
        const bf16* Bh = st + 2 * FA_ELE;
        const bf16* Bl = st + 3 * FA_ELE;

#pragma unroll
        for (int kk = 0; kk < KC; kk += 16) {
            uint32_t ah[2][4], al[2][4];
#pragma unroll
            for (int i = 0; i < 2; i++) {
                int row = wm * 32 + i * 16 + (lane & 15);
                int col = kk + ((lane >> 4) << 3);
                ldsm4(ah[i][0], ah[i][1], ah[i][2], ah[i][3], Ah + row * LDT + col);
                ldsm4(al[i][0], al[i][1], al[i][2], al[i][3], Al + row * LDT + col);
            }
            int brow = wn * 16 + (lane & 7) + ((lane >> 4) << 3);
            int col = kk + (((lane >> 3) & 1) << 3);
            uint32_t bh[4], bl[4];
            ldsm4(bh[0], bh[1], bh[2], bh[3], Bh + brow * LDT + col);
            ldsm4(bl[0], bl[1], bl[2], bl[3], Bl + brow * LDT + col);
#pragma unroll
            for (int i = 0; i < 2; i++) {
#pragma unroll
                for (int q = 0; q < 2; q++) {
                    float* d = acc[i][q];
                    mma16816(d, ah[i][0], ah[i][1], ah[i][2], ah[i][3], bh[2*q], bh[2*q+1]);
                    mma16816(d, ah[i][0], ah[i][1], ah[i][2], ah[i][3], bl[2*q], bl[2*q+1]);
                    mma16816(d, al[i][0], al[i][1], al[i][2], al[i][3], bh[2*q], bh[2*q+1]);
                }
            }
        }
    }

    // epilogue: write fp32 out[b][t][o] and tiled decoder-input splits
#pragma unroll
    for (int i = 0; i < 2; i++) {
#pragma unroll
        for (int j = 0; j < 2; j++) {
            int r0 = m0 + wm * 32 + i * 16 + (lane >> 2);
            int c0 = n0 + wn * 16 + j * 8 + ((lane & 3) << 1);
#pragma unroll
            for (int half = 0; half < 2; half++) {
                int r = r0 + half * 8;
                float v0 = acc[i][j][half * 2]     + b_fc[c0];
                float v1 = acc[i][j][half * 2 + 1] + b_fc[c0 + 1];
                out[(size_t)r * (HOR * O_) + t * O_ + c0]     = v0;
                out[(size_t)r * (HOR * O_) + t * O_ + c0 + 1] = v1;
                int dt = ((c0 >> 5) * 256 + r) * 32 + (c0 & 31);
                split2(v0, g_dit_hi[dt],     g_dit_lo[dt]);
                split2(v1, g_dit_hi[dt + 1], g_dit_lo[dt + 1]);
            }
        }
    }
}

// ---------------- launch ----------------
extern "C" void kernel_launch(void* const* d_in, const int* in_sizes, int n_in,
                              void* d_out, int out_size) {
    const float* x    = (const float*)d_in[0];
    const float* W_ih = (const float*)d_in[1];
    const float* W_hh = (const float*)d_in[2];
    const float* b_ih = (const float*)d_in[3];
    const float* b_hh = (const float*)d_in[4];
    const float* W_fc = (const float*)d_in[5];
    const float* b_fc = (const float*)d_in[6];
    float* out = (float*)d_out;

    cudaFuncSetAttribute(gemm_cell_kernel,
                         cudaFuncAttributeMaxDynamicSharedMemorySize, SMEM_GC_BYTES);
    cudaFuncSetAttribute(fc_kernel,
                         cudaFuncAttributeMaxDynamicSharedMemorySize, SMEM_FC_BYTES);

    prep_wc_kernel<<<4096, 256>>>(W_ih, W_hh);
    prep_wfc_kernel<<<1024, 256>>>(W_fc);
    prep_x_kernel<<<4096, 256>>>(x);
    prep_state_kernel<<<512, 256>>>(b_ih, b_hh);

    dim3 ggrid(H_ / BN, B_ / BM);   // (32, 4) = 128 CTAs
    dim3 fgrid(O_ / 64, B_ / 64);   // (16, 4)

    int par = 0;
    for (int t = 0; t < S_; t++) {
        gemm_cell_kernel<<<ggrid, 256, SMEM_GC_BYTES>>>(t, 0, par);
        par ^= 1;
    }
    for (int d = 0; d < HOR; d++) {
        fc_kernel<<<fgrid, 256, SMEM_FC_BYTES>>>(out, b_fc, d, par);
        gemm_cell_kernel<<<ggrid, 256, SMEM_GC_BYTES>>>(0, 1, par);
        par ^= 1;
    }
}